// round 7
// baseline (speedup 1.0000x reference)
#include <cuda_runtime.h>
#include <cstdint>

#define Gg   100
#define G3   1000000
#define HW   327680      // (1280/2)*(1024/2) = 640*512
#define HMW2 640
#define Bsz  2
#define Csz  8
#define Jsz  12

__global__ __launch_bounds__(256, 4) void reproj_kernel(
    const float* __restrict__ hm,      // [B,C,J,512,640]
    const float* __restrict__ center,  // [B,3]
    const float* __restrict__ Mg,      // [B,C,4,3]
    const float* __restrict__ intr,    // [B,C,3,3]
    const float* __restrict__ dist,    // [B,C,1,5]
    float* __restrict__ out)           // [B,J,100,100,100]
{
    __shared__ float sM[Csz][12];
    __shared__ float sPar[Csz][8];   // fx, fy, cx, cy, k1, k2, 1/fx, 1/fy

    const int b = blockIdx.y;
    const int t = threadIdx.x;

    if (t < Csz * 12) {
        sM[t / 12][t % 12] = Mg[b * Csz * 12 + t];
    } else if (t < Csz * 12 + Csz) {
        const int c = t - Csz * 12;
        const float* ic = intr + (b * Csz + c) * 9;
        const float fx = ic[0], fy = ic[4];
        sPar[c][0] = fx;
        sPar[c][1] = fy;
        sPar[c][2] = ic[6];   // cx
        sPar[c][3] = ic[7];   // cy
        const float* dc = dist + (b * Csz + c) * 5;
        sPar[c][4] = dc[0];   // k1
        sPar[c][5] = dc[1];   // k2
        sPar[c][6] = __frcp_rn(fx);  // hoisted reciprocal (loop-invariant)
        sPar[c][7] = __frcp_rn(fy);
    }
    __syncthreads();

    const int n = blockIdx.x * 256 + t;
    if (n >= G3) return;

    // n = i*G*G + j*G + k ; point = (coords[i], coords[j], coords[k]) + center
    const int i  = n / (Gg * Gg);
    const int r0 = n - i * (Gg * Gg);
    const int jg = r0 / Gg;
    const int kg = r0 - jg * Gg;

    const float x = __fadd_rn((float)(i  - 50) * 2.0f, center[b * 3 + 0]);
    const float y = __fadd_rn((float)(jg - 50) * 2.0f, center[b * 3 + 1]);
    const float z = __fadd_rn((float)(kg - 50) * 2.0f, center[b * 3 + 2]);

    float acc[Jsz];
#pragma unroll
    for (int j = 0; j < Jsz; j++) acc[j] = 0.0f;

#pragma unroll
    for (int c = 0; c < Csz; c++) {
        const float* M = sM[c];

        // Eigen gebp K=4: four accumulators (rounded products), pairwise combine:
        //   p = ((x*M0) + (y*M1)) + ((z*M2) + M3)
        float p0 = __fadd_rn(__fadd_rn(__fmul_rn(x, M[0]), __fmul_rn(y, M[3])),
                             __fadd_rn(__fmul_rn(z, M[6]), M[9]));
        float p1 = __fadd_rn(__fadd_rn(__fmul_rn(x, M[1]), __fmul_rn(y, M[4])),
                             __fadd_rn(__fmul_rn(z, M[7]), M[10]));
        float p2 = __fadd_rn(__fadd_rn(__fmul_rn(x, M[2]), __fmul_rn(y, M[5])),
                             __fadd_rn(__fmul_rn(z, M[8]), M[11]));

        // Reciprocal-multiply division (arcp-style): shared rn(1/p2)
        const float rp2 = __frcp_rn(p2);
        const float px  = __fmul_rn(p0, rp2);
        const float py  = __fmul_rn(p1, rp2);

        const float fx = sPar[c][0], fy = sPar[c][1];
        const float cx = sPar[c][2], cy = sPar[c][3];
        const float k1 = sPar[c][4], k2 = sPar[c][5];
        const float rfx = sPar[c][6], rfy = sPar[c][7];

        const float xn = __fmul_rn(__fsub_rn(px, cx), rfx);
        const float yn = __fmul_rn(__fsub_rn(py, cy), rfy);

        // r2 = xn*xn + yn*yn  (no contraction)
        const float r2 = __fadd_rn(__fmul_rn(xn, xn), __fmul_rn(yn, yn));
        // rad = (1 + k1*r2) + (k2*r2)*r2  (left-assoc, no contraction)
        const float rad = __fadd_rn(__fadd_rn(1.0f, __fmul_rn(k1, r2)),
                                    __fmul_rn(__fmul_rn(k2, r2), r2));

        // xd = ((xn*rad)*fx) + cx  (no contraction), clip
        float xd = __fadd_rn(__fmul_rn(__fmul_rn(xn, rad), fx), cx);
        float yd = __fadd_rn(__fmul_rn(__fmul_rn(yn, rad), fy), cy);
        xd = fminf(fmaxf(xd, 0.0f), 1279.0f);
        yd = fminf(fmaxf(yd, 0.0f), 1023.0f);

        // idx = int(yd/2)*640 + int(xd/2)  (×0.5 exact; trunc == floor for >=0)
        const int idx = (int)(yd * 0.5f) * HMW2 + (int)(xd * 0.5f);

        const float* hbase = hm + (size_t)(b * Csz + c) * Jsz * HW + idx;
#pragma unroll
        for (int j = 0; j < Jsz; j++)
            acc[j] = __fadd_rn(acc[j], __ldg(hbase + (size_t)j * HW));
    }

    float* ob = out + (size_t)b * Jsz * G3 + n;
#pragma unroll
    for (int j = 0; j < Jsz; j++)
        ob[(size_t)j * G3] = acc[j] * 0.125f;   // mean over C=8 (exact)
}

extern "C" void kernel_launch(void* const* d_in, const int* in_sizes, int n_in,
                              void* d_out, int out_size)
{
    const float* hm     = (const float*)d_in[0];
    const float* center = (const float*)d_in[1];
    const float* Mg     = (const float*)d_in[2];
    const float* intr   = (const float*)d_in[3];
    const float* dist   = (const float*)d_in[4];
    float* out = (float*)d_out;

    dim3 grid((G3 + 255) / 256, Bsz);
    reproj_kernel<<<grid, 256>>>(hm, center, Mg, intr, dist, out);
}